// round 10
// baseline (speedup 1.0000x reference)
#include <cuda_runtime.h>
#include <cuda_bf16.h>
#include <cstdint>

#define BDIM 16384
#define HDIM 1024
#define KTOT 2048
#define MT   128            // CTA M tile
#define NPT  256            // CTA permuted-N tile (4 gates x 64)
#define BK   32             // K per stage
#define NITER (KTOT / BK)   // 64
#define THREADS 512

// padded smem row: 32 + 8 bf16 = 80 bytes (20 words -> conflict-free frags)
#define ROWB 80
#define ASZ  (MT  * ROWB)   // 10240
#define BSZ  (NPT * ROWB)   // 20480
#define STG  (2 * ASZ + 2 * BSZ)   // 61440
#define NSTAGE 3
#define SMEM_TOTAL (NSTAGE * STG)  // 184320

// ---------------- scratch (device globals) ----------------
__device__ __nv_bfloat16 g_Ahi[(size_t)BDIM * KTOT];
__device__ __nv_bfloat16 g_Alo[(size_t)BDIM * KTOT];
__device__ __nv_bfloat16 g_Whi[(size_t)4 * HDIM * KTOT];  // [ntile16][gate4][64][K]
__device__ __nv_bfloat16 g_Wlo[(size_t)4 * HDIM * KTOT];

// ---------------- helpers ----------------
__device__ __forceinline__ uint32_t smem_u32(const void* p) {
    uint32_t a;
    asm("{ .reg .u64 t; cvta.to.shared.u64 t, %1; cvt.u32.u64 %0, t; }" : "=r"(a) : "l"(p));
    return a;
}
#define CP_ASYNC16(dst, src) \
    asm volatile("cp.async.cg.shared.global [%0], [%1], 16;" :: "r"((uint32_t)(dst)), "l"(src) : "memory")
#define CP_COMMIT() asm volatile("cp.async.commit_group;" ::: "memory")
#define CP_WAIT(n)  asm volatile("cp.async.wait_group %0;" :: "n"(n) : "memory")

__device__ __forceinline__ void mma16816(float* d, const uint32_t* a, const uint32_t* b) {
    asm volatile("mma.sync.aligned.m16n8k16.row.col.f32.bf16.bf16.f32 "
        "{%0,%1,%2,%3}, {%4,%5,%6,%7}, {%8,%9}, {%0,%1,%2,%3};"
        : "+f"(d[0]), "+f"(d[1]), "+f"(d[2]), "+f"(d[3])
        : "r"(a[0]), "r"(a[1]), "r"(a[2]), "r"(a[3]), "r"(b[0]), "r"(b[1]));
}
__device__ __forceinline__ void ldsm4(uint32_t* r, uint32_t addr) {
    asm volatile("ldmatrix.sync.aligned.m8n8.x4.shared.b16 {%0,%1,%2,%3}, [%4];"
        : "=r"(r[0]), "=r"(r[1]), "=r"(r[2]), "=r"(r[3]) : "r"(addr));
}

// ---------------- conversion prepass ----------------
__device__ __forceinline__ void cvt8(const float* v, uint4& uh, uint4& ul) {
    uint32_t hw[4], lw[4];
    #pragma unroll
    for (int p = 0; p < 4; p++) {
        float a = v[2 * p], b = v[2 * p + 1];
        __nv_bfloat16 ah = __float2bfloat16(a), bh = __float2bfloat16(b);
        __nv_bfloat16 al = __float2bfloat16(a - __bfloat162float(ah));
        __nv_bfloat16 bl = __float2bfloat16(b - __bfloat162float(bh));
        hw[p] = (uint32_t)__bfloat16_as_ushort(ah) | ((uint32_t)__bfloat16_as_ushort(bh) << 16);
        lw[p] = (uint32_t)__bfloat16_as_ushort(al) | ((uint32_t)__bfloat16_as_ushort(bl) << 16);
    }
    uh = make_uint4(hw[0], hw[1], hw[2], hw[3]);
    ul = make_uint4(lw[0], lw[1], lw[2], lw[3]);
}

__global__ __launch_bounds__(256)
void conv_A_kernel(const float* __restrict__ x, const float* __restrict__ h) {
    size_t i = ((size_t)blockIdx.x * 256 + threadIdx.x) * 8;
    int m = (int)(i >> 11);
    int k = (int)(i & 2047);
    const float* src = (k < 1024) ? (x + (size_t)m * 1024 + k)
                                  : (h + (size_t)m * 1024 + (k - 1024));
    float v[8];
    *(float4*)(v)     = *(const float4*)(src);
    *(float4*)(v + 4) = *(const float4*)(src + 4);
    uint4 uh, ul;
    cvt8(v, uh, ul);
    *(uint4*)(g_Ahi + i) = uh;
    *(uint4*)(g_Alo + i) = ul;
}

__global__ __launch_bounds__(256)
void conv_W_kernel(const float* __restrict__ Wix, const float* __restrict__ Wfx,
                   const float* __restrict__ Wcx, const float* __restrict__ Wox,
                   const float* __restrict__ Wih, const float* __restrict__ Wfh,
                   const float* __restrict__ Wch, const float* __restrict__ Woh) {
    size_t i = ((size_t)blockIdx.x * 256 + threadIdx.x) * 8;
    int rp = (int)(i >> 11);
    int k  = (int)(i & 2047);
    int ntile = rp >> 8, rem = rp & 255, g = rem >> 6, nl = rem & 63;
    int n = ntile * 64 + nl;
    const float* Wx; const float* Wh;
    if      (g == 0) { Wx = Wix; Wh = Wih; }
    else if (g == 1) { Wx = Wfx; Wh = Wfh; }
    else if (g == 2) { Wx = Wcx; Wh = Wch; }
    else             { Wx = Wox; Wh = Woh; }
    const float* src = (k < 1024) ? (Wx + (size_t)n * 1024 + k)
                                  : (Wh + (size_t)n * 1024 + (k - 1024));
    float v[8];
    *(float4*)(v)     = *(const float4*)(src);
    *(float4*)(v + 4) = *(const float4*)(src + 4);
    uint4 uh, ul;
    cvt8(v, uh, ul);
    *(uint4*)(g_Whi + i) = uh;
    *(uint4*)(g_Wlo + i) = ul;
}

// ---------------- main GEMM + fused LSTM epilogue ----------------
// 16 warps: warp_m = wid&3 (32-row slice), warp_n = wid>>2 (= gate, 64 cols)
__global__ __launch_bounds__(THREADS, 1)
void lstm_mma_kernel(const float* __restrict__ c_prev,
                     const float* __restrict__ bix, const float* __restrict__ bih,
                     const float* __restrict__ bfx, const float* __restrict__ bfh,
                     const float* __restrict__ bcx, const float* __restrict__ bch,
                     const float* __restrict__ box_, const float* __restrict__ boh,
                     float* __restrict__ out) {
    extern __shared__ __align__(128) char smem[];
    const uint32_t su = smem_u32(smem);
    const int tid = threadIdx.x;
    const int wid = tid >> 5, lane = tid & 31;
    const int g = lane >> 2, tq = lane & 3;
    const int warp_m = wid & 3;           // 0..3 (32 rows each)
    const int warp_n = wid >> 2;          // 0..3 == gate
    const int m0 = blockIdx.y * MT;
    const int bx = blockIdx.x;            // n-tile
    const int n0 = bx * 64;

    const __nv_bfloat16* Abase_h = g_Ahi + (size_t)m0 * KTOT;
    const __nv_bfloat16* Abase_l = g_Alo + (size_t)m0 * KTOT;
    const __nv_bfloat16* Wbase_h = g_Whi + (size_t)bx * NPT * KTOT;
    const __nv_bfloat16* Wbase_l = g_Wlo + (size_t)bx * NPT * KTOT;

    float acc[2][8][4];
    #pragma unroll
    for (int a = 0; a < 2; a++)
        #pragma unroll
        for (int b = 0; b < 8; b++)
            #pragma unroll
            for (int c = 0; c < 4; c++) acc[a][b][c] = 0.f;

    // ---- pipeline loads: 6 cp.async per thread per stage ----
    auto load_stage = [&](int t, int s) {
        const int k0 = t * BK;
        const uint32_t st = su + (uint32_t)s * STG;
        {                                                   // A hi/lo: 512 chunks each
            int row = tid >> 2, cc = tid & 3;
            const __nv_bfloat16* sh = Abase_h + (size_t)row * KTOT + k0 + cc * 8;
            const __nv_bfloat16* sl = Abase_l + (size_t)row * KTOT + k0 + cc * 8;
            uint32_t off = (uint32_t)row * ROWB + cc * 16;
            CP_ASYNC16(st + off,        sh);
            CP_ASYNC16(st + ASZ + off,  sl);
        }
        #pragma unroll
        for (int rep = 0; rep < 2; rep++) {                 // B hi/lo: 1024 chunks each
            int i = tid + rep * 512;
            int row = i >> 2, cc = i & 3;
            const __nv_bfloat16* sh = Wbase_h + (size_t)row * KTOT + k0 + cc * 8;
            const __nv_bfloat16* sl = Wbase_l + (size_t)row * KTOT + k0 + cc * 8;
            uint32_t off = (uint32_t)row * ROWB + cc * 16;
            CP_ASYNC16(st + 2 * ASZ + off,        sh);
            CP_ASYNC16(st + 2 * ASZ + BSZ + off,  sl);
        }
        CP_COMMIT();
    };

    load_stage(0, 0);
    load_stage(1, 1);

    // ldmatrix per-lane address components
    const int grp = lane >> 3, lr = lane & 7;
    const uint32_t aRowOff = (uint32_t)(warp_m * 32 + ((grp & 1) << 3) + lr);
    const uint32_t aKoff   = (uint32_t)((grp >> 1) << 4);
    const uint32_t bRowOff = (uint32_t)(warp_n * 64 + ((grp >> 1) << 3) + lr);
    const uint32_t bKoff   = (uint32_t)((grp & 1) << 4);

    #pragma unroll 1
    for (int t = 0; t < NITER; t++) {
        if (t < NITER - 1) CP_WAIT(1); else CP_WAIT(0);
        __syncthreads();
        if (t + 2 < NITER) load_stage(t + 2, (t + 2) % NSTAGE);

        const uint32_t st = su + (uint32_t)(t % NSTAGE) * STG;
        const uint32_t uAh = st, uAl = st + ASZ, uBh = st + 2 * ASZ, uBl = st + 2 * ASZ + BSZ;

        #pragma unroll
        for (int kt = 0; kt < 2; kt++) {
            const uint32_t kb = (uint32_t)(kt * 32);
            uint32_t afh[2][4], afl[2][4], bfh[4][4], bfl[4][4];
            #pragma unroll
            for (int tm = 0; tm < 2; tm++) {
                uint32_t r = (aRowOff + 16 * tm) * ROWB + kb + aKoff;
                ldsm4(afh[tm], uAh + r);
                ldsm4(afl[tm], uAl + r);
            }
            #pragma unroll
            for (int p = 0; p < 4; p++) {
                uint32_t r = (bRowOff + 16 * p) * ROWB + kb + bKoff;
                ldsm4(bfh[p], uBh + r);
                ldsm4(bfl[p], uBl + r);
            }
            #pragma unroll
            for (int tm = 0; tm < 2; tm++)
                #pragma unroll
                for (int tn = 0; tn < 8; tn++) {
                    const uint32_t* bh = &bfh[tn >> 1][(tn & 1) * 2];
                    const uint32_t* bl = &bfl[tn >> 1][(tn & 1) * 2];
                    mma16816(acc[tm][tn], afh[tm], bh);
                    mma16816(acc[tm][tn], afh[tm], bl);
                    mma16816(acc[tm][tn], afl[tm], bh);
                }
        }
    }
    __syncthreads();

    // ---- epilogue: combine 4 gates through smem, fuse LSTM math ----
    // 16 regions of 32x68 floats: region = warp_m*4 + gate; biases after
    float* eg   = (float*)smem;
    float* bsum = (float*)(smem + 16 * 32 * 68 * 4);      // 139264
    const uint32_t egBase = (uint32_t)((warp_m * 4 + warp_n) * 32 * 68);

    #pragma unroll
    for (int tm = 0; tm < 2; tm++)
        #pragma unroll
        for (int tn = 0; tn < 8; tn++) {
            uint32_t r0 = egBase + (uint32_t)(16 * tm + g) * 68 + 8 * tn + tq * 2;
            eg[r0]            = acc[tm][tn][0];
            eg[r0 + 1]        = acc[tm][tn][1];
            eg[r0 + 8 * 68]     = acc[tm][tn][2];
            eg[r0 + 8 * 68 + 1] = acc[tm][tn][3];
        }
    if (tid < 64) {
        int n = n0 + tid;
        bsum[tid]       = bix[n] + bih[n];
        bsum[64 + tid]  = bfx[n] + bfh[n];
        bsum[128 + tid] = bcx[n] + bch[n];
        bsum[192 + tid] = box_[n] + boh[n];
    }
    __syncthreads();

    #pragma unroll
    for (int it = 0; it < 16; it++) {
        int idx = tid + it * 512;          // 0..8191
        int row = idx >> 6, col = idx & 63;
        int wm = row >> 5, r = row & 31;
        const float* base = eg + (size_t)(wm * 4) * 32 * 68 + (size_t)r * 68 + col;
        float I = base[0]              + bsum[col];
        float F = base[32 * 68]        + bsum[64 + col];
        float G = tanhf(base[2 * 32 * 68] + bsum[128 + col]);
        float O = base[3 * 32 * 68]    + bsum[192 + col];
        size_t go = (size_t)(m0 + row) * HDIM + n0 + col;
        float cn = G * I + c_prev[go] * F;
        out[go] = O * tanhf(cn);
        out[(size_t)BDIM * HDIM + go] = cn;
    }
}

// ---------------- launch ----------------
extern "C" void kernel_launch(void* const* d_in, const int* in_sizes, int n_in,
                              void* d_out, int out_size) {
    const float* x      = (const float*)d_in[0];
    const float* h      = (const float*)d_in[1];
    const float* c_prev = (const float*)d_in[2];
    const float* Wix = (const float*)d_in[3];  const float* bix  = (const float*)d_in[4];
    const float* Wfx = (const float*)d_in[5];  const float* bfx  = (const float*)d_in[6];
    const float* Wcx = (const float*)d_in[7];  const float* bcx  = (const float*)d_in[8];
    const float* Wox = (const float*)d_in[9];  const float* box_ = (const float*)d_in[10];
    const float* Wih = (const float*)d_in[11]; const float* bih  = (const float*)d_in[12];
    const float* Wfh = (const float*)d_in[13]; const float* bfh  = (const float*)d_in[14];
    const float* Wch = (const float*)d_in[15]; const float* bch  = (const float*)d_in[16];
    const float* Woh = (const float*)d_in[17]; const float* boh  = (const float*)d_in[18];
    float* out = (float*)d_out;

    conv_A_kernel<<<BDIM * KTOT / 8 / 256, 256>>>(x, h);
    conv_W_kernel<<<4 * HDIM * KTOT / 8 / 256, 256>>>(Wix, Wfx, Wcx, Wox, Wih, Wfh, Wch, Woh);

    cudaFuncSetAttribute(lstm_mma_kernel, cudaFuncAttributeMaxDynamicSharedMemorySize, SMEM_TOTAL);
    dim3 grid(HDIM / 64, BDIM / MT);   // (16, 128)
    lstm_mma_kernel<<<grid, THREADS, SMEM_TOTAL>>>(c_prev,
        bix, bih, bfx, bfh, bcx, bch, box_, boh, out);
}

// round 12
// speedup vs baseline: 1.4226x; 1.4226x over previous
#include <cuda_runtime.h>
#include <cuda_fp16.h>
#include <cstdint>

#define BDIM 16384
#define HDIM 1024
#define KTOT 2048
#define MT   128            // CTA M tile
#define NPT  256            // CTA permuted-N tile (4 gates x 64)
#define BK   32             // K per stage
#define NITER (KTOT / BK)   // 64
#define THREADS 256

// padded smem row: 32 fp16 (64B) + 16B pad = 80 bytes
#define ROWB 80
#define ASZ  (MT  * ROWB)   // 10240
#define BSZ  (NPT * ROWB)   // 20480
#define STG  (2 * ASZ + BSZ)       // 40960 (Ah, Al, Bh)
#define NSTAGE 3
#define SMEM_TOTAL 140288   // max(3*STG=122880, epilogue 139264+1024)

// ---------------- scratch (device globals) ----------------
__device__ __half g_Ah[(size_t)BDIM * KTOT];
__device__ __half g_Al[(size_t)BDIM * KTOT];
__device__ __half g_Wh[(size_t)4 * HDIM * KTOT];   // [ntile16][gate4][64][K]

// ---------------- helpers ----------------
__device__ __forceinline__ uint32_t smem_u32(const void* p) {
    uint32_t a;
    asm("{ .reg .u64 t; cvta.to.shared.u64 t, %1; cvt.u32.u64 %0, t; }" : "=r"(a) : "l"(p));
    return a;
}
#define CP_ASYNC16(dst, src) \
    asm volatile("cp.async.cg.shared.global [%0], [%1], 16;" :: "r"((uint32_t)(dst)), "l"(src) : "memory")
#define CP_COMMIT() asm volatile("cp.async.commit_group;" ::: "memory")
#define CP_WAIT(n)  asm volatile("cp.async.wait_group %0;" :: "n"(n) : "memory")

__device__ __forceinline__ void mma16816h(float* d, const uint32_t* a, const uint32_t* b) {
    asm volatile("mma.sync.aligned.m16n8k16.row.col.f32.f16.f16.f32 "
        "{%0,%1,%2,%3}, {%4,%5,%6,%7}, {%8,%9}, {%0,%1,%2,%3};"
        : "+f"(d[0]), "+f"(d[1]), "+f"(d[2]), "+f"(d[3])
        : "r"(a[0]), "r"(a[1]), "r"(a[2]), "r"(a[3]), "r"(b[0]), "r"(b[1]));
}
__device__ __forceinline__ void ldsm4(uint32_t* r, uint32_t addr) {
    asm volatile("ldmatrix.sync.aligned.m8n8.x4.shared.b16 {%0,%1,%2,%3}, [%4];"
        : "=r"(r[0]), "=r"(r[1]), "=r"(r[2]), "=r"(r[3]) : "r"(addr));
}

// ---------------- conversion prepasses ----------------
// A: 2-term fp16 split (exact to ~2^-22)
__global__ __launch_bounds__(256)
void conv_A_kernel(const float* __restrict__ x, const float* __restrict__ h) {
    size_t i = ((size_t)blockIdx.x * 256 + threadIdx.x) * 8;
    int m = (int)(i >> 11);
    int k = (int)(i & 2047);
    const float* src = (k < 1024) ? (x + (size_t)m * 1024 + k)
                                  : (h + (size_t)m * 1024 + (k - 1024));
    float v[8];
    *(float4*)(v)     = *(const float4*)(src);
    *(float4*)(v + 4) = *(const float4*)(src + 4);
    uint32_t hw[4], lw[4];
    #pragma unroll
    for (int p = 0; p < 4; p++) {
        float a = v[2 * p], b = v[2 * p + 1];
        __half ah = __float2half_rn(a), bh = __float2half_rn(b);
        __half al = __float2half_rn(a - __half2float(ah));
        __half bl = __float2half_rn(b - __half2float(bh));
        hw[p] = (uint32_t)__half_as_ushort(ah) | ((uint32_t)__half_as_ushort(bh) << 16);
        lw[p] = (uint32_t)__half_as_ushort(al) | ((uint32_t)__half_as_ushort(bl) << 16);
    }
    *(uint4*)(g_Ah + i) = make_uint4(hw[0], hw[1], hw[2], hw[3]);
    *(uint4*)(g_Al + i) = make_uint4(lw[0], lw[1], lw[2], lw[3]);
}

// W: single fp16 (quantization err ~2^-12 rel — the only numerics loss)
__global__ __launch_bounds__(256)
void conv_W_kernel(const float* __restrict__ Wix, const float* __restrict__ Wfx,
                   const float* __restrict__ Wcx, const float* __restrict__ Wox,
                   const float* __restrict__ Wih, const float* __restrict__ Wfh,
                   const float* __restrict__ Wch, const float* __restrict__ Woh) {
    size_t i = ((size_t)blockIdx.x * 256 + threadIdx.x) * 8;
    int rp = (int)(i >> 11);
    int k  = (int)(i & 2047);
    int ntile = rp >> 8, rem = rp & 255, g = rem >> 6, nl = rem & 63;
    int n = ntile * 64 + nl;
    const float* Wx; const float* Wh;
    if      (g == 0) { Wx = Wix; Wh = Wih; }
    else if (g == 1) { Wx = Wfx; Wh = Wfh; }
    else if (g == 2) { Wx = Wcx; Wh = Wch; }
    else             { Wx = Wox; Wh = Woh; }
    const float* src = (k < 1024) ? (Wx + (size_t)n * 1024 + k)
                                  : (Wh + (size_t)n * 1024 + (k - 1024));
    float v[8];
    *(float4*)(v)     = *(const float4*)(src);
    *(float4*)(v + 4) = *(const float4*)(src + 4);
    uint32_t hw[4];
    #pragma unroll
    for (int p = 0; p < 4; p++) {
        hw[p] = (uint32_t)__half_as_ushort(__float2half_rn(v[2 * p]))
              | ((uint32_t)__half_as_ushort(__float2half_rn(v[2 * p + 1])) << 16);
    }
    *(uint4*)(g_Wh + i) = make_uint4(hw[0], hw[1], hw[2], hw[3]);
}

// ---------------- main GEMM + fused LSTM epilogue ----------------
__global__ __launch_bounds__(THREADS, 1)
void lstm_mma_kernel(const float* __restrict__ c_prev,
                     const float* __restrict__ bix, const float* __restrict__ bih,
                     const float* __restrict__ bfx, const float* __restrict__ bfh,
                     const float* __restrict__ bcx, const float* __restrict__ bch,
                     const float* __restrict__ box_, const float* __restrict__ boh,
                     float* __restrict__ out) {
    extern __shared__ __align__(128) char smem[];
    const uint32_t su = smem_u32(smem);
    const int tid = threadIdx.x;
    const int wid = tid >> 5, lane = tid & 31;
    const int g = lane >> 2, tq = lane & 3;
    const int warp_m = wid >> 2;          // 0..1 (64 rows)
    const int warp_n = wid & 3;           // 0..3 == gate
    const int m0 = blockIdx.y * MT;
    const int bx = blockIdx.x;            // n-tile
    const int n0 = bx * 64;

    const __half* Abase_h = g_Ah + (size_t)m0 * KTOT;
    const __half* Abase_l = g_Al + (size_t)m0 * KTOT;
    const __half* Wbase_h = g_Wh + (size_t)bx * NPT * KTOT;

    float acc[4][8][4];
    #pragma unroll
    for (int a = 0; a < 4; a++)
        #pragma unroll
        for (int b = 0; b < 8; b++)
            #pragma unroll
            for (int c = 0; c < 4; c++) acc[a][b][c] = 0.f;

    // ---- pipeline loads: 8 cp.async per thread per stage ----
    auto load_stage = [&](int t, int s) {
        const int k0 = t * BK;
        const uint32_t st = su + (uint32_t)s * STG;
        #pragma unroll
        for (int rep = 0; rep < 2; rep++) {                 // A hi/lo: 512 chunks each
            int i = tid + rep * 256;
            int row = i >> 2, cc = i & 3;
            const __half* sh = Abase_h + (size_t)row * KTOT + k0 + cc * 8;
            const __half* sl = Abase_l + (size_t)row * KTOT + k0 + cc * 8;
            uint32_t off = (uint32_t)row * ROWB + cc * 16;
            CP_ASYNC16(st + off,        sh);
            CP_ASYNC16(st + ASZ + off,  sl);
        }
        #pragma unroll
        for (int rep = 0; rep < 4; rep++) {                 // B hi: 1024 chunks
            int i = tid + rep * 256;
            int row = i >> 2, cc = i & 3;
            const __half* sh = Wbase_h + (size_t)row * KTOT + k0 + cc * 8;
            uint32_t off = (uint32_t)row * ROWB + cc * 16;
            CP_ASYNC16(st + 2 * ASZ + off, sh);
        }
        CP_COMMIT();
    };

    load_stage(0, 0);
    load_stage(1, 1);

    // ldmatrix per-lane address components
    const int grp = lane >> 3, lr = lane & 7;
    const uint32_t aRowOff = (uint32_t)(warp_m * 64 + ((grp & 1) << 3) + lr);
    const uint32_t aKoff   = (uint32_t)((grp >> 1) << 4);
    const uint32_t bRowOff = (uint32_t)(warp_n * 64 + ((grp >> 1) << 3) + lr);
    const uint32_t bKoff   = (uint32_t)((grp & 1) << 4);

    #pragma unroll 1
    for (int t = 0; t < NITER; t++) {
        if (t < NITER - 1) CP_WAIT(1); else CP_WAIT(0);
        __syncthreads();
        if (t + 2 < NITER) load_stage(t + 2, (t + 2) % NSTAGE);

        const uint32_t st = su + (uint32_t)(t % NSTAGE) * STG;
        const uint32_t uAh = st, uAl = st + ASZ, uBh = st + 2 * ASZ;

        #pragma unroll
        for (int kt = 0; kt < 2; kt++) {
            const uint32_t kb = (uint32_t)(kt * 32);
            uint32_t afh[4][4], afl[4][4], bfh[4][4];
            #pragma unroll
            for (int tm = 0; tm < 4; tm++) {
                uint32_t r = (aRowOff + 16 * tm) * ROWB + kb + aKoff;
                ldsm4(afh[tm], uAh + r);
                ldsm4(afl[tm], uAl + r);
            }
            #pragma unroll
            for (int p = 0; p < 4; p++) {
                uint32_t r = (bRowOff + 16 * p) * ROWB + kb + bKoff;
                ldsm4(bfh[p], uBh + r);
            }
            #pragma unroll
            for (int tm = 0; tm < 4; tm++)
                #pragma unroll
                for (int tn = 0; tn < 8; tn++) {
                    const uint32_t* bh = &bfh[tn >> 1][(tn & 1) * 2];
                    mma16816h(acc[tm][tn], afh[tm], bh);
                    mma16816h(acc[tm][tn], afl[tm], bh);
                }
        }
    }
    __syncthreads();

    // ---- epilogue: combine 4 gates through smem, fuse LSTM math ----
    float* eg   = (float*)smem;
    float* bsum = (float*)(smem + 2 * 4 * 64 * 68 * 4);   // 139264
    const uint32_t egBase = (uint32_t)((warp_m * 4 + warp_n) * 64 * 68);

    #pragma unroll
    for (int tm = 0; tm < 4; tm++)
        #pragma unroll
        for (int tn = 0; tn < 8; tn++) {
            uint32_t r0 = egBase + (uint32_t)(16 * tm + g) * 68 + 8 * tn + tq * 2;
            eg[r0]            = acc[tm][tn][0];
            eg[r0 + 1]        = acc[tm][tn][1];
            eg[r0 + 8 * 68]     = acc[tm][tn][2];
            eg[r0 + 8 * 68 + 1] = acc[tm][tn][3];
        }
    if (tid < 64) {
        int n = n0 + tid;
        bsum[tid]       = bix[n] + bih[n];
        bsum[64 + tid]  = bfx[n] + bfh[n];
        bsum[128 + tid] = bcx[n] + bch[n];
        bsum[192 + tid] = box_[n] + boh[n];
    }
    __syncthreads();

    #pragma unroll
    for (int it = 0; it < 32; it++) {
        int idx = tid + it * 256;          // 0..8191
        int row = idx >> 6, col = idx & 63;
        int wm = row >> 6, r = row & 63;
        const float* base = eg + (size_t)wm * 4 * 64 * 68 + (size_t)r * 68 + col;
        float I = base[0]            + bsum[col];
        float F = base[64 * 68]      + bsum[64 + col];
        float G = tanhf(base[2 * 64 * 68] + bsum[128 + col]);
        float O = base[3 * 64 * 68]  + bsum[192 + col];
        size_t go = (size_t)(m0 + row) * HDIM + n0 + col;
        float cn = G * I + c_prev[go] * F;
        out[go] = O * tanhf(cn);
        out[(size_t)BDIM * HDIM + go] = cn;
    }
}

// ---------------- launch ----------------
extern "C" void kernel_launch(void* const* d_in, const int* in_sizes, int n_in,
                              void* d_out, int out_size) {
    const float* x      = (const float*)d_in[0];
    const float* h      = (const float*)d_in[1];
    const float* c_prev = (const float*)d_in[2];
    const float* Wix = (const float*)d_in[3];  const float* bix  = (const float*)d_in[4];
    const float* Wfx = (const float*)d_in[5];  const float* bfx  = (const float*)d_in[6];
    const float* Wcx = (const float*)d_in[7];  const float* bcx  = (const float*)d_in[8];
    const float* Wox = (const float*)d_in[9];  const float* box_ = (const float*)d_in[10];
    const float* Wih = (const float*)d_in[11]; const float* bih  = (const float*)d_in[12];
    const float* Wfh = (const float*)d_in[13]; const float* bfh  = (const float*)d_in[14];
    const float* Wch = (const float*)d_in[15]; const float* bch  = (const float*)d_in[16];
    const float* Woh = (const float*)d_in[17]; const float* boh  = (const float*)d_in[18];
    float* out = (float*)d_out;

    conv_A_kernel<<<BDIM * KTOT / 8 / 256, 256>>>(x, h);
    conv_W_kernel<<<4 * HDIM * KTOT / 8 / 256, 256>>>(Wix, Wfx, Wcx, Wox, Wih, Wfh, Wch, Woh);

    cudaFuncSetAttribute(lstm_mma_kernel, cudaFuncAttributeMaxDynamicSharedMemorySize, SMEM_TOTAL);
    dim3 grid(HDIM / 64, BDIM / MT);   // (16, 128)
    lstm_mma_kernel<<<grid, THREADS, SMEM_TOTAL>>>(c_prev,
        bix, bih, bfx, bfh, bcx, bch, box_, boh, out);
}

// round 17
// speedup vs baseline: 2.2868x; 1.6074x over previous
#include <cuda_runtime.h>
#include <cuda_fp16.h>
#include <cstdint>

#define BDIM 16384
#define HDIM 1024
#define KTOT 2048
#define MT   128            // CTA M tile
#define NPT  256            // CTA permuted-N tile (4 gates x 64)
#define BK   32             // K per stage
#define NITER (KTOT / BK)   // 64
#define THREADS 256

// padded smem row: 32 fp16 (64B) + 16B pad = 80 bytes
#define ROWB 80
#define ASZ  (MT  * ROWB)   // 10240
#define BSZ  (NPT * ROWB)   // 20480
#define STG  (ASZ + BSZ)    // 30720 (Ah, Bh)
#define NSTAGE 3
#define SMEM_TOTAL 140288   // max(3*STG=92160, epilogue 139264+1024)

// ---------------- scratch (device globals) ----------------
__device__ __half g_Ah[(size_t)BDIM * KTOT];
__device__ __half g_Wh[(size_t)4 * HDIM * KTOT];   // [ntile16][gate4][64][K]

// ---------------- helpers ----------------
__device__ __forceinline__ uint32_t smem_u32(const void* p) {
    uint32_t a;
    asm("{ .reg .u64 t; cvta.to.shared.u64 t, %1; cvt.u32.u64 %0, t; }" : "=r"(a) : "l"(p));
    return a;
}
#define CP_ASYNC16(dst, src) \
    asm volatile("cp.async.cg.shared.global [%0], [%1], 16;" :: "r"((uint32_t)(dst)), "l"(src) : "memory")
#define CP_COMMIT() asm volatile("cp.async.commit_group;" ::: "memory")
#define CP_WAIT(n)  asm volatile("cp.async.wait_group %0;" :: "n"(n) : "memory")

__device__ __forceinline__ void mma16816h(float* d, const uint32_t* a, const uint32_t* b) {
    asm volatile("mma.sync.aligned.m16n8k16.row.col.f32.f16.f16.f32 "
        "{%0,%1,%2,%3}, {%4,%5,%6,%7}, {%8,%9}, {%0,%1,%2,%3};"
        : "+f"(d[0]), "+f"(d[1]), "+f"(d[2]), "+f"(d[3])
        : "r"(a[0]), "r"(a[1]), "r"(a[2]), "r"(a[3]), "r"(b[0]), "r"(b[1]));
}
__device__ __forceinline__ void ldsm4(uint32_t* r, uint32_t addr) {
    asm volatile("ldmatrix.sync.aligned.m8n8.x4.shared.b16 {%0,%1,%2,%3}, [%4];"
        : "=r"(r[0]), "=r"(r[1]), "=r"(r[2]), "=r"(r[3]) : "r"(addr));
}

// ---------------- conversion prepasses ----------------
// A: single fp16 (rn) — quantization err ~2^-12 rms rel
__global__ __launch_bounds__(256)
void conv_A_kernel(const float* __restrict__ x, const float* __restrict__ h) {
    size_t i = ((size_t)blockIdx.x * 256 + threadIdx.x) * 8;
    int m = (int)(i >> 11);
    int k = (int)(i & 2047);
    const float* src = (k < 1024) ? (x + (size_t)m * 1024 + k)
                                  : (h + (size_t)m * 1024 + (k - 1024));
    float v[8];
    *(float4*)(v)     = *(const float4*)(src);
    *(float4*)(v + 4) = *(const float4*)(src + 4);
    uint32_t hw[4];
    #pragma unroll
    for (int p = 0; p < 4; p++) {
        hw[p] = (uint32_t)__half_as_ushort(__float2half_rn(v[2 * p]))
              | ((uint32_t)__half_as_ushort(__float2half_rn(v[2 * p + 1])) << 16);
    }
    *(uint4*)(g_Ah + i) = make_uint4(hw[0], hw[1], hw[2], hw[3]);
}

// W: single fp16
__global__ __launch_bounds__(256)
void conv_W_kernel(const float* __restrict__ Wix, const float* __restrict__ Wfx,
                   const float* __restrict__ Wcx, const float* __restrict__ Wox,
                   const float* __restrict__ Wih, const float* __restrict__ Wfh,
                   const float* __restrict__ Wch, const float* __restrict__ Woh) {
    size_t i = ((size_t)blockIdx.x * 256 + threadIdx.x) * 8;
    int rp = (int)(i >> 11);
    int k  = (int)(i & 2047);
    int ntile = rp >> 8, rem = rp & 255, g = rem >> 6, nl = rem & 63;
    int n = ntile * 64 + nl;
    const float* Wx; const float* Wh;
    if      (g == 0) { Wx = Wix; Wh = Wih; }
    else if (g == 1) { Wx = Wfx; Wh = Wfh; }
    else if (g == 2) { Wx = Wcx; Wh = Wch; }
    else             { Wx = Wox; Wh = Woh; }
    const float* src = (k < 1024) ? (Wx + (size_t)n * 1024 + k)
                                  : (Wh + (size_t)n * 1024 + (k - 1024));
    float v[8];
    *(float4*)(v)     = *(const float4*)(src);
    *(float4*)(v + 4) = *(const float4*)(src + 4);
    uint32_t hw[4];
    #pragma unroll
    for (int p = 0; p < 4; p++) {
        hw[p] = (uint32_t)__half_as_ushort(__float2half_rn(v[2 * p]))
              | ((uint32_t)__half_as_ushort(__float2half_rn(v[2 * p + 1])) << 16);
    }
    *(uint4*)(g_Wh + i) = make_uint4(hw[0], hw[1], hw[2], hw[3]);
}

// ---------------- main GEMM + fused LSTM epilogue ----------------
__global__ __launch_bounds__(THREADS, 1)
void lstm_mma_kernel(const float* __restrict__ c_prev,
                     const float* __restrict__ bix, const float* __restrict__ bih,
                     const float* __restrict__ bfx, const float* __restrict__ bfh,
                     const float* __restrict__ bcx, const float* __restrict__ bch,
                     const float* __restrict__ box_, const float* __restrict__ boh,
                     float* __restrict__ out) {
    extern __shared__ __align__(128) char smem[];
    const uint32_t su = smem_u32(smem);
    const int tid = threadIdx.x;
    const int wid = tid >> 5, lane = tid & 31;
    const int g = lane >> 2, tq = lane & 3;
    const int warp_m = wid >> 2;          // 0..1 (64 rows)
    const int warp_n = wid & 3;           // 0..3 == gate
    const int m0 = blockIdx.y * MT;
    const int bx = blockIdx.x;            // n-tile
    const int n0 = bx * 64;

    const __half* Abase_h = g_Ah + (size_t)m0 * KTOT;
    const __half* Wbase_h = g_Wh + (size_t)bx * NPT * KTOT;

    float acc[4][8][4];
    #pragma unroll
    for (int a = 0; a < 4; a++)
        #pragma unroll
        for (int b = 0; b < 8; b++)
            #pragma unroll
            for (int c = 0; c < 4; c++) acc[a][b][c] = 0.f;

    // ---- pipeline loads: 6 cp.async per thread per stage ----
    auto load_stage = [&](int t, int s) {
        const int k0 = t * BK;
        const uint32_t st = su + (uint32_t)s * STG;
        #pragma unroll
        for (int rep = 0; rep < 2; rep++) {                 // A: 512 chunks
            int i = tid + rep * 256;
            int row = i >> 2, cc = i & 3;
            const __half* sh = Abase_h + (size_t)row * KTOT + k0 + cc * 8;
            uint32_t off = (uint32_t)row * ROWB + cc * 16;
            CP_ASYNC16(st + off, sh);
        }
        #pragma unroll
        for (int rep = 0; rep < 4; rep++) {                 // B: 1024 chunks
            int i = tid + rep * 256;
            int row = i >> 2, cc = i & 3;
            const __half* sh = Wbase_h + (size_t)row * KTOT + k0 + cc * 8;
            uint32_t off = (uint32_t)row * ROWB + cc * 16;
            CP_ASYNC16(st + ASZ + off, sh);
        }
        CP_COMMIT();
    };

    load_stage(0, 0);
    load_stage(1, 1);

    // ldmatrix per-lane address components
    const int grp = lane >> 3, lr = lane & 7;
    const uint32_t aRowOff = (uint32_t)(warp_m * 64 + ((grp & 1) << 3) + lr);
    const uint32_t aKoff   = (uint32_t)((grp >> 1) << 4);
    const uint32_t bRowOff = (uint32_t)(warp_n * 64 + ((grp >> 1) << 3) + lr);
    const uint32_t bKoff   = (uint32_t)((grp & 1) << 4);

    #pragma unroll 1
    for (int t = 0; t < NITER; t++) {
        if (t < NITER - 1) CP_WAIT(1); else CP_WAIT(0);
        __syncthreads();
        if (t + 2 < NITER) load_stage(t + 2, (t + 2) % NSTAGE);

        const uint32_t st = su + (uint32_t)(t % NSTAGE) * STG;
        const uint32_t uAh = st, uBh = st + ASZ;

        #pragma unroll
        for (int kt = 0; kt < 2; kt++) {
            const uint32_t kb = (uint32_t)(kt * 32);
            uint32_t afh[4][4], bfh[4][4];
            #pragma unroll
            for (int tm = 0; tm < 4; tm++) {
                uint32_t r = (aRowOff + 16 * tm) * ROWB + kb + aKoff;
                ldsm4(afh[tm], uAh + r);
            }
            #pragma unroll
            for (int p = 0; p < 4; p++) {
                uint32_t r = (bRowOff + 16 * p) * ROWB + kb + bKoff;
                ldsm4(bfh[p], uBh + r);
            }
            #pragma unroll
            for (int tm = 0; tm < 4; tm++)
                #pragma unroll
                for (int tn = 0; tn < 8; tn++) {
                    const uint32_t* bh = &bfh[tn >> 1][(tn & 1) * 2];
                    mma16816h(acc[tm][tn], afh[tm], bh);
                }
        }
    }
    __syncthreads();

    // ---- epilogue: combine 4 gates through smem, fuse LSTM math ----
    float* eg   = (float*)smem;
    float* bsum = (float*)(smem + 2 * 4 * 64 * 68 * 4);   // 139264
    const uint32_t egBase = (uint32_t)((warp_m * 4 + warp_n) * 64 * 68);

    #pragma unroll
    for (int tm = 0; tm < 4; tm++)
        #pragma unroll
        for (int tn = 0; tn < 8; tn++) {
            uint32_t r0 = egBase + (uint32_t)(16 * tm + g) * 68 + 8 * tn + tq * 2;
            eg[r0]            = acc[tm][tn][0];
            eg[r0 + 1]        = acc[tm][tn][1];
            eg[r0 + 8 * 68]     = acc[tm][tn][2];
            eg[r0 + 8 * 68 + 1] = acc[tm][tn][3];
        }
    if (tid < 64) {
        int n = n0 + tid;
        bsum[tid]       = bix[n] + bih[n];
        bsum[64 + tid]  = bfx[n] + bfh[n];
        bsum[128 + tid] = bcx[n] + bch[n];
        bsum[192 + tid] = box_[n] + boh[n];
    }
    __syncthreads();

    #pragma unroll
    for (int it = 0; it < 32; it++) {
        int idx = tid + it * 256;          // 0..8191
        int row = idx >> 6, col = idx & 63;
        int wm = row >> 6, r = row & 63;
        const float* base = eg + (size_t)wm * 4 * 64 * 68 + (size_t)r * 68 + col;
        float I = base[0]            + bsum[col];
        float F = base[64 * 68]      + bsum[64 + col];
        float G = tanhf(base[2 * 64 * 68] + bsum[128 + col]);
        float O = base[3 * 64 * 68]  + bsum[192 + col];
        size_t go = (size_t)(m0 + row) * HDIM + n0 + col;
        float cn = G * I + c_prev[go] * F;
        out[go] = O * tanhf(cn);
        out[(size_t)BDIM * HDIM + go] = cn;
    }
}

// ---------------- launch ----------------
extern "C" void kernel_launch(void* const* d_in, const int* in_sizes, int n_in,
                              void* d_out, int out_size) {
    const float* x      = (const float*)d_in[0];
    const float* h      = (const float*)d_in[1];
    const float* c_prev = (const float*)d_in[2];
    const float* Wix = (const float*)d_in[3];  const float* bix  = (const float*)d_in[4];
    const float* Wfx = (const float*)d_in[5];  const float* bfx  = (const float*)d_in[6];
    const float* Wcx = (const float*)d_in[7];  const float* bcx  = (const float*)d_in[8];
    const float* Wox = (const float*)d_in[9];  const float* box_ = (const float*)d_in[10];
    const float* Wih = (const float*)d_in[11]; const float* bih  = (const float*)d_in[12];
    const float* Wfh = (const float*)d_in[13]; const float* bfh  = (const float*)d_in[14];
    const float* Wch = (const float*)d_in[15]; const float* bch  = (const float*)d_in[16];
    const float* Woh = (const float*)d_in[17]; const float* boh  = (const float*)d_in[18];
    float* out = (float*)d_out;

    conv_A_kernel<<<BDIM * KTOT / 8 / 256, 256>>>(x, h);
    conv_W_kernel<<<4 * HDIM * KTOT / 8 / 256, 256>>>(Wix, Wfx, Wcx, Wox, Wih, Wfh, Wch, Woh);

    cudaFuncSetAttribute(lstm_mma_kernel, cudaFuncAttributeMaxDynamicSharedMemorySize, SMEM_TOTAL);
    dim3 grid(HDIM / 64, BDIM / MT);   // (16, 128)
    lstm_mma_kernel<<<grid, THREADS, SMEM_TOTAL>>>(c_prev,
        bix, bih, bfx, bfh, bcx, bch, box_, boh, out);
}